// round 4
// baseline (speedup 1.0000x reference)
#include <cuda_runtime.h>
#include <cstdint>

// Problem shape (fixed for this dataset entry)
#define BB 8
#define CC 81
#define HH 96
#define WW 320
#define NN 16
#define HWSZ (HH * WW)            // 30720
#define TILE 512                  // pixels per block
#define STAGES 9                  // 81 = 9*9, exact
#define TPB 256

#define ALPHA_F   0.25f
#define FG_W_F    13.0f
#define BG_W_F    1.0f
#define DEPTH_MIN_F 0.001f
#define DEPTH_MAX_F 60.0f
#define NUM_BINS_I  80

__device__ __forceinline__ uint32_t smem_u32(const void* p) {
    uint32_t a;
    asm("{ .reg .u64 t; cvta.to.shared.u64 t, %1; cvt.u32.u64 %0, t; }"
        : "=r"(a) : "l"(p));
    return a;
}

__global__ __launch_bounds__(TPB) void ddn_loss_kernel(
    const float* __restrict__ logits,   // (B,C,H,W)
    const float* __restrict__ boxes,    // (B*N,4)
    const float* __restrict__ depths,   // (B*N,)
    float* __restrict__ out)            // scalar
{
    __shared__ float stage[STAGES][TILE];       // 18432 B
    __shared__ int   sbu1[NN], sbv1[NN], sbu2[NN], sbv2[NN];
    __shared__ float sdep[NN];
    __shared__ float sred[8];

    const int tile = blockIdx.x;                 // 0..479
    const int tiles_per_b = HWSZ / TILE;         // 60
    const int b    = tile / tiles_per_b;
    const int pix0 = (tile - b * tiles_per_b) * TILE;
    const int t    = threadIdx.x;
    const int pix  = pix0 + 2 * t;               // even; pair never crosses a row (W even)
    const int h    = pix / WW;
    const int w0   = pix - h * WW;

    if (t < NN) {
        const int i = b * NN + t;
        sbu1[t] = (int)floorf(boxes[4 * i + 0]);
        sbv1[t] = (int)floorf(boxes[4 * i + 1]);
        sbu2[t] = (int)ceilf (boxes[4 * i + 2]);
        sbv2[t] = (int)ceilf (boxes[4 * i + 3]);
        sdep[t] = depths[i];
    }
    __syncthreads();

    // ---- Rasterize + LID binning for this thread's 2 pixels ----
    int   tgt[2];
    float wgt[2];
#pragma unroll
    for (int j = 0; j < 2; j++) {
        const int w = w0 + j;
        float dmin = 1e10f;
        bool  fg   = false;
#pragma unroll
        for (int i = 0; i < NN; i++) {
            const bool cov = (h >= sbv1[i]) & (h < sbv2[i]) &
                             (w >= sbu1[i]) & (w < sbu2[i]);
            if (cov) { fg = true; dmin = fminf(dmin, sdep[i]); }
        }
        const float d = fg ? dmin : 0.0f;
        const float bin_size = 2.0f * (DEPTH_MAX_F - DEPTH_MIN_F)
                               / ((float)NUM_BINS_I * (1.0f + (float)NUM_BINS_I));
        float idx = -0.5f + 0.5f * sqrtf(1.0f + 8.0f * (d - DEPTH_MIN_F) / bin_size);
        if (!(idx >= 0.0f) || idx > (float)NUM_BINS_I) idx = (float)NUM_BINS_I;
        tgt[j] = (int)idx;
        wgt[j] = fg ? FG_W_F : BG_W_F;
    }

    // This thread's 2 floats for channel 0
    const float* gsrc = logits + (size_t)b * CC * HWSZ + pix;

    // Target logits fetched up front (plain LDG, overlaps with pipeline fill)
    const float xt0 = gsrc[(size_t)tgt[0] * HWSZ];
    const float xt1 = gsrc[(size_t)tgt[1] * HWSZ + 1];

    // ---- cp.async pipeline: thread t loads & consumes only its own 8 B/stage ----
    const uint32_t dbase = smem_u32(&stage[0][2 * t]);

#pragma unroll
    for (int s = 0; s < STAGES; s++) {
        const uint32_t d = dbase + s * (TILE * 4);
        asm volatile("cp.async.ca.shared.global [%0], [%1], 8;\n"
                     :: "r"(d), "l"(gsrc + (size_t)s * HWSZ) : "memory");
        asm volatile("cp.async.commit_group;\n" ::: "memory");
    }

    float s0 = 0.f, s1 = 0.f;
    for (int cc = 0; cc < CC; cc += STAGES) {
#pragma unroll
        for (int i = 0; i < STAGES; i++) {
            asm volatile("cp.async.wait_group 8;\n" ::: "memory");
            const float2 x = *(const float2*)&stage[i][2 * t];
            const int cn = cc + i + STAGES;
            if (cn < CC) {
                const uint32_t d = dbase + i * (TILE * 4);
                asm volatile("cp.async.ca.shared.global [%0], [%1], 8;\n"
                             :: "r"(d), "l"(gsrc + (size_t)cn * HWSZ) : "memory");
            }
            asm volatile("cp.async.commit_group;\n" ::: "memory");
            s0 += __expf(x.x);
            s1 += __expf(x.y);
        }
    }

    // ---- Focal loss per pixel, weighted ----
    float local = 0.f;
    {
        float lp, pt;
        lp = xt0 - __logf(s0); pt = __expf(lp);
        local += wgt[0] * (-ALPHA_F * (1.f - pt) * (1.f - pt) * lp);
        lp = xt1 - __logf(s1); pt = __expf(lp);
        local += wgt[1] * (-ALPHA_F * (1.f - pt) * (1.f - pt) * lp);
    }

    // ---- Block reduction -> one atomic per block ----
#pragma unroll
    for (int o = 16; o > 0; o >>= 1)
        local += __shfl_xor_sync(0xffffffffu, local, o);
    if ((t & 31) == 0) sred[t >> 5] = local;
    __syncthreads();
    if (t < 8) {
        float v = sred[t];
#pragma unroll
        for (int o = 4; o > 0; o >>= 1)
            v += __shfl_xor_sync(0x000000ffu, v, o);
        if (t == 0) {
            const float inv_np = 1.0f / (float)(BB * HH * WW);
            atomicAdd(out, v * inv_np);
        }
    }
}

extern "C" void kernel_launch(void* const* d_in, const int* in_sizes, int n_in,
                              void* d_out, int out_size) {
    const float* logits = (const float*)d_in[0];   // depth_logits (B,C,H,W) f32
    const float* boxes  = (const float*)d_in[1];   // gt_boxes2d (B*N,4) f32
    // d_in[2] = num_gt_per_img (scalar int, constant 16 for this shape)
    const float* depths = (const float*)d_in[3];   // gt_center_depth (B*N,) f32
    float* out = (float*)d_out;

    cudaMemsetAsync(out, 0, sizeof(float), 0);

    const int blocks = BB * HWSZ / TILE;           // 480 tiles, single wave
    ddn_loss_kernel<<<blocks, TPB>>>(logits, boxes, depths, out);
}

// round 5
// speedup vs baseline: 1.2373x; 1.2373x over previous
#include <cuda_runtime.h>
#include <cstdint>

// Problem shape (fixed for this dataset entry)
#define BB 8
#define CC 81
#define HH 96
#define WW 320
#define NN 16
#define HWSZ (HH * WW)            // 30720
#define TPB 256
#define BATCH 9                   // 81 = 9*9

#define ALPHA_F   0.25f
#define FG_W_F    13.0f
#define BG_W_F    1.0f
#define DEPTH_MIN_F 0.001f
#define DEPTH_MAX_F 60.0f
#define NUM_BINS_I  80

__global__ __launch_bounds__(TPB, 6) void ddn_loss_kernel(
    const float* __restrict__ logits,   // (B,C,H,W)
    const float* __restrict__ boxes,    // (B*N,4)
    const float* __restrict__ depths,   // (B*N,)
    float* __restrict__ out)            // scalar
{
    __shared__ int   sbu1[NN], sbv1[NN], sbu2[NN], sbv2[NN];
    __shared__ float sdep[NN];
    __shared__ float sred[8];

    const int t   = threadIdx.x;
    const int g   = blockIdx.x * TPB + t;        // 0..245759, one pixel per thread
    const int b   = g / HWSZ;                    // blocks never cross batch (30720 % 256 == 0)
    const int rem = g - b * HWSZ;
    const int h   = rem / WW;
    const int w   = rem - h * WW;

    if (t < NN) {
        const int i = b * NN + t;
        sbu1[t] = (int)floorf(boxes[4 * i + 0]);
        sbv1[t] = (int)floorf(boxes[4 * i + 1]);
        sbu2[t] = (int)ceilf (boxes[4 * i + 2]);
        sbv2[t] = (int)ceilf (boxes[4 * i + 3]);
        sdep[t] = depths[i];
    }
    __syncthreads();

    // ---- Rasterize + LID binning for this thread's pixel ----
    float dmin = 1e10f;
    bool  fg   = false;
#pragma unroll
    for (int i = 0; i < NN; i++) {
        const bool cov = (h >= sbv1[i]) & (h < sbv2[i]) &
                         (w >= sbu1[i]) & (w < sbu2[i]);
        if (cov) { fg = true; dmin = fminf(dmin, sdep[i]); }
    }
    const float d = fg ? dmin : 0.0f;
    const float wgt = fg ? FG_W_F : BG_W_F;
    const float bin_size = 2.0f * (DEPTH_MAX_F - DEPTH_MIN_F)
                           / ((float)NUM_BINS_I * (1.0f + (float)NUM_BINS_I));
    float idxf = -0.5f + 0.5f * sqrtf(1.0f + 8.0f * (d - DEPTH_MIN_F) / bin_size);
    if (!(idxf >= 0.0f) || idxf > (float)NUM_BINS_I) idxf = (float)NUM_BINS_I;
    const int tgt = (int)idxf;                    // truncation toward zero

    // Base of this pixel within batch b's plane stack
    const float* __restrict__ gsrc = logits + (size_t)b * CC * HWSZ + rem;

    // Target logit fetched up front (line also touched by the stream; L2 hit)
    const float xt = gsrc[(size_t)tgt * HWSZ];

    // ---- Stream 81 channels: 9-deep double-buffered register pipeline ----
    float cur[BATCH], nxt[BATCH];
#pragma unroll
    for (int i = 0; i < BATCH; i++)
        cur[i] = gsrc[(size_t)i * HWSZ];

    float s = 0.f;
#pragma unroll 1
    for (int blk = 0; blk < CC / BATCH - 1; blk++) {
        const float* p = gsrc + (size_t)(blk + 1) * BATCH * HWSZ;
#pragma unroll
        for (int i = 0; i < BATCH; i++)          // issue next batch first (stays in flight)
            nxt[i] = p[(size_t)i * HWSZ];
#pragma unroll
        for (int i = 0; i < BATCH; i++)          // consume current batch
            s += __expf(cur[i]);
#pragma unroll
        for (int i = 0; i < BATCH; i++)
            cur[i] = nxt[i];
    }
#pragma unroll
    for (int i = 0; i < BATCH; i++)
        s += __expf(cur[i]);

    // ---- Focal loss, weighted ----
    const float lp = xt - __logf(s);
    const float pt = __expf(lp);
    float local = wgt * (-ALPHA_F * (1.f - pt) * (1.f - pt) * lp);

    // ---- Block reduction -> one atomic per block ----
#pragma unroll
    for (int o = 16; o > 0; o >>= 1)
        local += __shfl_xor_sync(0xffffffffu, local, o);
    if ((t & 31) == 0) sred[t >> 5] = local;
    __syncthreads();
    if (t < 8) {
        float v = sred[t];
#pragma unroll
        for (int o = 4; o > 0; o >>= 1)
            v += __shfl_xor_sync(0x000000ffu, v, o);
        if (t == 0) {
            const float inv_np = 1.0f / (float)(BB * HH * WW);
            atomicAdd(out, v * inv_np);
        }
    }
}

extern "C" void kernel_launch(void* const* d_in, const int* in_sizes, int n_in,
                              void* d_out, int out_size) {
    const float* logits = (const float*)d_in[0];   // depth_logits (B,C,H,W) f32
    const float* boxes  = (const float*)d_in[1];   // gt_boxes2d (B*N,4) f32
    // d_in[2] = num_gt_per_img (scalar int, constant 16 for this shape)
    const float* depths = (const float*)d_in[3];   // gt_center_depth (B*N,) f32
    float* out = (float*)d_out;

    cudaMemsetAsync(out, 0, sizeof(float), 0);

    const int blocks = BB * HWSZ / TPB;            // 960
    ddn_loss_kernel<<<blocks, TPB>>>(logits, boxes, depths, out);
}